// round 1
// baseline (speedup 1.0000x reference)
#include <cuda_runtime.h>
#include <cstdint>
#include <math.h>

// ---------------- problem constants (fixed shapes from setup_inputs) ----------------
#define NN   50000
#define F0   128     // layer0 input features
#define H0   4       // layer0 heads
#define C0   64      // layer0 per-head channels
#define HC0  256     // H0*C0
#define HC1  64      // layer1 output features (1 head * 64)

// ---------------- scratch (static device globals; no allocation) ----------------
__device__ float g_h0  [(size_t)NN * HC0];   // layer0 linear output / later relu(out0+b0)
__device__ float g_acc0[(size_t)NN * HC0];   // layer0 aggregated messages
__device__ float g_as0 [NN * H0];
__device__ float g_ad0 [NN * H0];
__device__ float g_emax0[NN * H0];
__device__ float g_den0 [NN * H0];
__device__ float g_h1  [(size_t)NN * HC1];
__device__ float g_acc1[(size_t)NN * HC1];
__device__ float g_as1 [NN];
__device__ float g_ad1 [NN];
__device__ float g_emax1[NN];
__device__ float g_den1 [NN];

// ---------------- small helpers ----------------
__device__ __forceinline__ void atomicMaxF(float* addr, float v) {
    if (v >= 0.0f) atomicMax((int*)addr, __float_as_int(v));
    else           atomicMin((unsigned int*)addr, __float_as_uint(v));
}

__device__ __forceinline__ void redAdd4(float* p, float a, float b, float c, float d) {
    asm volatile("red.global.add.v4.f32 [%0], {%1,%2,%3,%4};"
                 :: "l"(p), "f"(a), "f"(b), "f"(c), "f"(d) : "memory");
}
__device__ __forceinline__ void redAdd2(float* p, float a, float b) {
    asm volatile("red.global.add.v2.f32 [%0], {%1,%2};"
                 :: "l"(p), "f"(a), "f"(b) : "memory");
}

__device__ __forceinline__ float leaky02(float v) { return v > 0.0f ? v : 0.2f * v; }

// ---------------- init kernels ----------------
__global__ void k_zero4(float4* p, int n4) {
    int i = blockIdx.x * blockDim.x + threadIdx.x;
    if (i < n4) p[i] = make_float4(0.f, 0.f, 0.f, 0.f);
}
__global__ void k_init_small() {
    int i = blockIdx.x * blockDim.x + threadIdx.x;
    if (i < NN * H0) { g_emax0[i] = -INFINITY; g_den0[i] = 0.f; }
    if (i < NN)      { g_emax1[i] = -INFINITY; g_den1[i] = 0.f; }
}

// ---------------- fp32 register-tiled GEMM:  C[M,Nc] = A[M,K] * B[Nc,K]^T ----------------
template<int BM, int BN, int BK, int TM, int TN>
__global__ void __launch_bounds__((BM/TM)*(BN/TN))
gemm_nt(const float* __restrict__ A, const float* __restrict__ B,
        float* __restrict__ C, int M, int Nc, int K)
{
    constexpr int THREADS = (BM/TM)*(BN/TN);
    constexpr int BMP = BM + 4;
    constexpr int BNP = BN + 4;
    __shared__ __align__(16) float As[BK][BMP];
    __shared__ __align__(16) float Bs[BK][BNP];

    const int tid = threadIdx.x;
    const int tx  = tid % (BN/TN);
    const int ty  = tid / (BN/TN);
    const int rowBase = blockIdx.x * BM;
    const int colBase = blockIdx.y * BN;

    float acc[TM][TN];
#pragma unroll
    for (int i = 0; i < TM; i++)
#pragma unroll
        for (int j = 0; j < TN; j++) acc[i][j] = 0.f;

    for (int k0 = 0; k0 < K; k0 += BK) {
        // --- load A tile (transposed into smem) ---
        constexpr int AF4 = BM * BK / 4;
#pragma unroll
        for (int i = 0; i < AF4 / THREADS; i++) {
            int f  = tid + i * THREADS;
            int r  = f / (BK/4);
            int c4 = f % (BK/4);
            float4 v = make_float4(0.f, 0.f, 0.f, 0.f);
            int gr = rowBase + r;
            if (gr < M) v = *(const float4*)(A + (size_t)gr * K + k0 + c4 * 4);
            As[c4*4+0][r] = v.x; As[c4*4+1][r] = v.y;
            As[c4*4+2][r] = v.z; As[c4*4+3][r] = v.w;
        }
        // --- load B tile ---
        constexpr int BF4 = BN * BK / 4;
#pragma unroll
        for (int i = 0; i < BF4 / THREADS; i++) {
            int f  = tid + i * THREADS;
            int r  = f / (BK/4);
            int c4 = f % (BK/4);
            float4 v = *(const float4*)(B + (size_t)(colBase + r) * K + k0 + c4 * 4);
            Bs[c4*4+0][r] = v.x; Bs[c4*4+1][r] = v.y;
            Bs[c4*4+2][r] = v.z; Bs[c4*4+3][r] = v.w;
        }
        __syncthreads();

#pragma unroll
        for (int k = 0; k < BK; k++) {
            float a[TM], b[TN];
            const float4* ap = (const float4*)&As[k][ty * TM];
            ((float4*)a)[0] = ap[0]; ((float4*)a)[1] = ap[1];
            const float4* bp = (const float4*)&Bs[k][tx * TN];
            ((float4*)b)[0] = bp[0]; ((float4*)b)[1] = bp[1];
#pragma unroll
            for (int i = 0; i < TM; i++)
#pragma unroll
                for (int j = 0; j < TN; j++)
                    acc[i][j] = fmaf(a[i], b[j], acc[i][j]);
        }
        __syncthreads();
    }

    // --- store ---
#pragma unroll
    for (int i = 0; i < TM; i++) {
        int gr = rowBase + ty * TM + i;
        if (gr < M) {
            float* cp = C + (size_t)gr * Nc + colBase + tx * TN;
#pragma unroll
            for (int j = 0; j < TN; j += 4)
                *(float4*)(cp + j) = make_float4(acc[i][j], acc[i][j+1], acc[i][j+2], acc[i][j+3]);
        }
    }
}

// ---------------- attention coefficients: as[n,h] = <h[n,h,:], att_s[h,:]> (C=64) ----------------
__global__ void k_coef(const float* __restrict__ h, const float* __restrict__ att_s,
                       const float* __restrict__ att_d, float* __restrict__ as_out,
                       float* __restrict__ ad_out, int Hh)
{
    int w    = (blockIdx.x * blockDim.x + threadIdx.x) >> 5;
    int lane = threadIdx.x & 31;
    int n    = w / Hh;
    int hd   = w % Hh;
    if (n >= NN) return;
    const float* row = h + (size_t)n * Hh * 64 + hd * 64;
    const float* asv = att_s + hd * 64;
    const float* adv = att_d + hd * 64;
    float s = row[lane] * asv[lane] + row[lane + 32] * asv[lane + 32];
    float d = row[lane] * adv[lane] + row[lane + 32] * adv[lane + 32];
#pragma unroll
    for (int o = 16; o; o >>= 1) {
        s += __shfl_down_sync(0xffffffffu, s, o);
        d += __shfl_down_sync(0xffffffffu, d, o);
    }
    if (lane == 0) { as_out[n * Hh + hd] = s; ad_out[n * Hh + hd] = d; }
}

// ---------------- edge kernels, layer 0 (H=4) ----------------
__device__ __forceinline__ void edge_sd(const int* __restrict__ ei, int e, int E, int& s, int& d) {
    if (e < E) { s = ei[e]; d = ei[E + e]; } else { s = e - E; d = e - E; }
}

__global__ void k_max4(const int* __restrict__ ei, int E, int Etot) {
    int e = blockIdx.x * blockDim.x + threadIdx.x;
    if (e >= Etot) return;
    int s, d; edge_sd(ei, e, E, s, d);
    float4 a = *(const float4*)(g_as0 + s * 4);
    float4 b = *(const float4*)(g_ad0 + d * 4);
    atomicMaxF(&g_emax0[d*4+0], leaky02(a.x + b.x));
    atomicMaxF(&g_emax0[d*4+1], leaky02(a.y + b.y));
    atomicMaxF(&g_emax0[d*4+2], leaky02(a.z + b.z));
    atomicMaxF(&g_emax0[d*4+3], leaky02(a.w + b.w));
}

__global__ void k_den4(const int* __restrict__ ei, int E, int Etot) {
    int e = blockIdx.x * blockDim.x + threadIdx.x;
    if (e >= Etot) return;
    int s, d; edge_sd(ei, e, E, s, d);
    float4 a = *(const float4*)(g_as0 + s * 4);
    float4 b = *(const float4*)(g_ad0 + d * 4);
    float4 m = *(const float4*)(g_emax0 + d * 4);
    atomicAdd(&g_den0[d*4+0], __expf(leaky02(a.x + b.x) - m.x));
    atomicAdd(&g_den0[d*4+1], __expf(leaky02(a.y + b.y) - m.y));
    atomicAdd(&g_den0[d*4+2], __expf(leaky02(a.z + b.z) - m.z));
    atomicAdd(&g_den0[d*4+3], __expf(leaky02(a.w + b.w) - m.w));
}

// warp per edge: 256 floats (8 per lane, head = lane/8)
__global__ void k_msg4(const int* __restrict__ ei, int E, int Etot) {
    int w = (blockIdx.x * blockDim.x + threadIdx.x) >> 5;
    if (w >= Etot) return;
    int lane = threadIdx.x & 31;
    int s, d; edge_sd(ei, w, E, s, d);
    int hd = lane >> 3;
    float v = leaky02(g_as0[s*4+hd] + g_ad0[d*4+hd]);
    float alpha = __expf(v - g_emax0[d*4+hd]) / (g_den0[d*4+hd] + 1e-16f);
    int off = lane * 8;
    const float4* hp = (const float4*)(g_h0 + (size_t)s * HC0 + off);
    float4 p0 = hp[0], p1 = hp[1];
    float* dp = g_acc0 + (size_t)d * HC0 + off;
    redAdd4(dp,     p0.x*alpha, p0.y*alpha, p0.z*alpha, p0.w*alpha);
    redAdd4(dp + 4, p1.x*alpha, p1.y*alpha, p1.z*alpha, p1.w*alpha);
}

// ---------------- edge kernels, layer 1 (H=1, C=64) ----------------
__global__ void k_max1(const int* __restrict__ ei, int E, int Etot) {
    int e = blockIdx.x * blockDim.x + threadIdx.x;
    if (e >= Etot) return;
    int s, d; edge_sd(ei, e, E, s, d);
    atomicMaxF(&g_emax1[d], leaky02(g_as1[s] + g_ad1[d]));
}
__global__ void k_den1(const int* __restrict__ ei, int E, int Etot) {
    int e = blockIdx.x * blockDim.x + threadIdx.x;
    if (e >= Etot) return;
    int s, d; edge_sd(ei, e, E, s, d);
    float v = leaky02(g_as1[s] + g_ad1[d]);
    atomicAdd(&g_den1[d], __expf(v - g_emax1[d]));
}
__global__ void k_msg1(const int* __restrict__ ei, int E, int Etot) {
    int w = (blockIdx.x * blockDim.x + threadIdx.x) >> 5;
    if (w >= Etot) return;
    int lane = threadIdx.x & 31;
    int s, d; edge_sd(ei, w, E, s, d);
    float v = leaky02(g_as1[s] + g_ad1[d]);
    float alpha = __expf(v - g_emax1[d]) / (g_den1[d] + 1e-16f);
    int off = lane * 2;
    float2 p = *(const float2*)(g_h1 + (size_t)s * HC1 + off);
    redAdd2(g_acc1 + (size_t)d * HC1 + off, p.x * alpha, p.y * alpha);
}

// ---------------- elementwise ----------------
__global__ void k_relu_bias(const float* __restrict__ b0) {
    int i = blockIdx.x * blockDim.x + threadIdx.x;
    if (i < NN * HC0)
        g_h0[i] = fmaxf(g_acc0[i] + b0[i & (HC0 - 1)], 0.f);
}
__global__ void k_final(const float* __restrict__ b1, float* __restrict__ out) {
    int i = blockIdx.x * blockDim.x + threadIdx.x;
    if (i < NN * HC1)
        out[i] = g_acc1[i] + b1[i & (HC1 - 1)];
}

// ---------------- launch ----------------
extern "C" void kernel_launch(void* const* d_in, const int* in_sizes, int n_in,
                              void* d_out, int out_size)
{
    const float* x      = (const float*)d_in[0];
    const int*   ei     = (const int*)  d_in[1];
    const float* W0     = (const float*)d_in[2];
    const float* att_s0 = (const float*)d_in[3];
    const float* att_d0 = (const float*)d_in[4];
    const float* b0     = (const float*)d_in[5];
    const float* W1     = (const float*)d_in[6];
    const float* att_s1 = (const float*)d_in[7];
    const float* att_d1 = (const float*)d_in[8];
    const float* b1     = (const float*)d_in[9];

    const int E    = in_sizes[1] / 2;
    const int Etot = E + NN;

    float *p_h0, *p_acc0, *p_h1, *p_acc1, *p_as0, *p_ad0, *p_as1, *p_ad1;
    cudaGetSymbolAddress((void**)&p_h0,   g_h0);
    cudaGetSymbolAddress((void**)&p_acc0, g_acc0);
    cudaGetSymbolAddress((void**)&p_h1,   g_h1);
    cudaGetSymbolAddress((void**)&p_acc1, g_acc1);
    cudaGetSymbolAddress((void**)&p_as0,  g_as0);
    cudaGetSymbolAddress((void**)&p_ad0,  g_ad0);
    cudaGetSymbolAddress((void**)&p_as1,  g_as1);
    cudaGetSymbolAddress((void**)&p_ad1,  g_ad1);

    const int TB = 256;
    // init scratch
    {
        int n4 = NN * HC0 / 4;
        k_zero4<<<(n4 + TB - 1) / TB, TB>>>((float4*)p_acc0, n4);
        n4 = NN * HC1 / 4;
        k_zero4<<<(n4 + TB - 1) / TB, TB>>>((float4*)p_acc1, n4);
        k_init_small<<<(NN * H0 + TB - 1) / TB, TB>>>();
    }

    // ---- layer 0 ----
    {
        dim3 grid((NN + 127) / 128, HC0 / 64);
        gemm_nt<128, 64, 32, 8, 8><<<grid, 128>>>(x, W0, p_h0, NN, HC0, F0);
    }
    {
        int warps = NN * H0;
        k_coef<<<(warps * 32 + TB - 1) / TB, TB>>>(p_h0, att_s0, att_d0, p_as0, p_ad0, H0);
    }
    k_max4<<<(Etot + TB - 1) / TB, TB>>>(ei, E, Etot);
    k_den4<<<(Etot + TB - 1) / TB, TB>>>(ei, E, Etot);
    {
        long long thr = (long long)Etot * 32;
        k_msg4<<<(int)((thr + TB - 1) / TB), TB>>>(ei, E, Etot);
    }
    k_relu_bias<<<(NN * HC0 + TB - 1) / TB, TB>>>(b0);

    // ---- layer 1 ----
    {
        dim3 grid((NN + 127) / 128, HC1 / 64);
        gemm_nt<128, 64, 32, 8, 8><<<grid, 128>>>(p_h0, W1, p_h1, NN, HC1, HC0);
    }
    {
        int warps = NN;
        k_coef<<<(warps * 32 + TB - 1) / TB, TB>>>(p_h1, att_s1, att_d1, p_as1, p_ad1, 1);
    }
    k_max1<<<(Etot + TB - 1) / TB, TB>>>(ei, E, Etot);
    k_den1<<<(Etot + TB - 1) / TB, TB>>>(ei, E, Etot);
    {
        long long thr = (long long)Etot * 32;
        k_msg1<<<(int)((thr + TB - 1) / TB), TB>>>(ei, E, Etot);
    }
    k_final<<<(NN * HC1 + TB - 1) / TB, TB>>>(b1, (float*)d_out);
}

// round 2
// speedup vs baseline: 1.5597x; 1.5597x over previous
#include <cuda_runtime.h>
#include <cstdint>
#include <math.h>

// ---------------- problem constants ----------------
#define NN    50000
#define F0    128
#define H0    4
#define HC0   256
#define HC1   64
#define EMAX  900000   // capacity for E + N self loops (E=800000, N=50000)

// ---------------- scratch ----------------
__device__ float g_lin0[(size_t)NN * HC0];  // gemm0 output (pre-aggregation features)
__device__ float g_feat[(size_t)NN * HC0];  // relu(agg0 + b0)  -> gemm1 input
__device__ float g_lin1[(size_t)NN * HC1];  // gemm1 output
__device__ float g_as0 [NN * H0];
__device__ float g_ad0 [NN * H0];
__device__ float g_as1 [NN];
__device__ float g_ad1 [NN];
__device__ int   g_deg [NN];
__device__ int   g_row [NN + 1];
__device__ int   g_cur [NN];
__device__ int   g_srcl[EMAX];

__device__ __forceinline__ float leaky02(float v) { return v > 0.0f ? v : 0.2f * v; }

__device__ __forceinline__ void edge_sd(const int* __restrict__ ei, int e, int E, int& s, int& d) {
    if (e < E) { s = ei[e]; d = ei[E + e]; } else { s = e - E; d = e - E; }
}

// ---------------- CSR build ----------------
__global__ void k_zero_deg() {
    int i = blockIdx.x * blockDim.x + threadIdx.x;
    if (i < NN) g_deg[i] = 0;
}
__global__ void k_hist(const int* __restrict__ ei, int E, int Etot) {
    int e = blockIdx.x * blockDim.x + threadIdx.x;
    if (e >= Etot) return;
    int s, d; edge_sd(ei, e, E, s, d);
    atomicAdd(&g_deg[d], 1);
}
// single-block exclusive scan over g_deg -> g_row, g_cur
__global__ void k_scan() {
    __shared__ int ssum[1024];
    const int t  = threadIdx.x;
    const int CH = (NN + 1023) / 1024;
    int beg = t * CH;
    int end = min(beg + CH, NN);
    int s = 0;
    for (int j = beg; j < end; j++) s += g_deg[j];
    ssum[t] = s;
    __syncthreads();
    for (int o = 1; o < 1024; o <<= 1) {
        int v = (t >= o) ? ssum[t - o] : 0;
        __syncthreads();
        ssum[t] += v;
        __syncthreads();
    }
    int run = (t == 0) ? 0 : ssum[t - 1];
    for (int j = beg; j < end; j++) {
        int dv = g_deg[j];
        g_row[j] = run;
        g_cur[j] = run;
        run += dv;
    }
    if (t == 1023) g_row[NN] = run;
}
__global__ void k_scatter(const int* __restrict__ ei, int E, int Etot) {
    int e = blockIdx.x * blockDim.x + threadIdx.x;
    if (e >= Etot) return;
    int s, d; edge_sd(ei, e, E, s, d);
    int pos = atomicAdd(&g_cur[d], 1);
    g_srcl[pos] = s;
}

// ---------------- fp32 register-tiled GEMM:  C[M,Nc] = A[M,K] * B[Nc,K]^T ----------------
template<int BM, int BN, int BK, int TM, int TN>
__global__ void __launch_bounds__((BM/TM)*(BN/TN))
gemm_nt(const float* __restrict__ A, const float* __restrict__ B,
        float* __restrict__ C, int M, int Nc, int K)
{
    constexpr int THREADS = (BM/TM)*(BN/TN);
    constexpr int BMP = BM + 4;
    constexpr int BNP = BN + 4;
    __shared__ __align__(16) float As[BK][BMP];
    __shared__ __align__(16) float Bs[BK][BNP];

    const int tid = threadIdx.x;
    const int tx  = tid % (BN/TN);
    const int ty  = tid / (BN/TN);
    const int rowBase = blockIdx.x * BM;
    const int colBase = blockIdx.y * BN;

    float acc[TM][TN];
#pragma unroll
    for (int i = 0; i < TM; i++)
#pragma unroll
        for (int j = 0; j < TN; j++) acc[i][j] = 0.f;

    for (int k0 = 0; k0 < K; k0 += BK) {
        constexpr int AF4 = BM * BK / 4;
#pragma unroll
        for (int i = 0; i < AF4 / THREADS; i++) {
            int f  = tid + i * THREADS;
            int r  = f / (BK/4);
            int c4 = f % (BK/4);
            float4 v = make_float4(0.f, 0.f, 0.f, 0.f);
            int gr = rowBase + r;
            if (gr < M) v = *(const float4*)(A + (size_t)gr * K + k0 + c4 * 4);
            As[c4*4+0][r] = v.x; As[c4*4+1][r] = v.y;
            As[c4*4+2][r] = v.z; As[c4*4+3][r] = v.w;
        }
        constexpr int BF4 = BN * BK / 4;
#pragma unroll
        for (int i = 0; i < BF4 / THREADS; i++) {
            int f  = tid + i * THREADS;
            int r  = f / (BK/4);
            int c4 = f % (BK/4);
            float4 v = *(const float4*)(B + (size_t)(colBase + r) * K + k0 + c4 * 4);
            Bs[c4*4+0][r] = v.x; Bs[c4*4+1][r] = v.y;
            Bs[c4*4+2][r] = v.z; Bs[c4*4+3][r] = v.w;
        }
        __syncthreads();

#pragma unroll
        for (int k = 0; k < BK; k++) {
            float a[TM], b[TN];
            const float4* ap = (const float4*)&As[k][ty * TM];
            ((float4*)a)[0] = ap[0]; ((float4*)a)[1] = ap[1];
            const float4* bp = (const float4*)&Bs[k][tx * TN];
            ((float4*)b)[0] = bp[0]; ((float4*)b)[1] = bp[1];
#pragma unroll
            for (int i = 0; i < TM; i++)
#pragma unroll
                for (int j = 0; j < TN; j++)
                    acc[i][j] = fmaf(a[i], b[j], acc[i][j]);
        }
        __syncthreads();
    }

#pragma unroll
    for (int i = 0; i < TM; i++) {
        int gr = rowBase + ty * TM + i;
        if (gr < M) {
            float* cp = C + (size_t)gr * Nc + colBase + tx * TN;
#pragma unroll
            for (int j = 0; j < TN; j += 4)
                *(float4*)(cp + j) = make_float4(acc[i][j], acc[i][j+1], acc[i][j+2], acc[i][j+3]);
        }
    }
}

// ---------------- attention coefficients ----------------
__global__ void k_coef(const float* __restrict__ h, const float* __restrict__ att_s,
                       const float* __restrict__ att_d, float* __restrict__ as_out,
                       float* __restrict__ ad_out, int Hh)
{
    int w    = (blockIdx.x * blockDim.x + threadIdx.x) >> 5;
    int lane = threadIdx.x & 31;
    int n    = w / Hh;
    int hd   = w % Hh;
    if (n >= NN) return;
    const float* row = h + (size_t)n * Hh * 64 + hd * 64;
    const float* asv = att_s + hd * 64;
    const float* adv = att_d + hd * 64;
    float s = row[lane] * asv[lane] + row[lane + 32] * asv[lane + 32];
    float d = row[lane] * adv[lane] + row[lane + 32] * adv[lane + 32];
#pragma unroll
    for (int o = 16; o; o >>= 1) {
        s += __shfl_down_sync(0xffffffffu, s, o);
        d += __shfl_down_sync(0xffffffffu, d, o);
    }
    if (lane == 0) { as_out[n * Hh + hd] = s; ad_out[n * Hh + hd] = d; }
}

// ---------------- CSR aggregation, layer 0: one warp per (dst, head) ----------------
// alpha = exp(e)/sum(exp(e)); no max-shift needed (e is O(1), no overflow).
__global__ void __launch_bounds__(256)
k_agg0(const float* __restrict__ b0)
{
    int w    = (blockIdx.x * blockDim.x + threadIdx.x) >> 5;
    int lane = threadIdx.x & 31;
    if (w >= NN * H0) return;
    int d = w >> 2;
    int h = w & 3;

    const int beg = g_row[d];
    const int n   = g_row[d + 1] - beg;
    const float ad = g_ad0[d * H0 + h];

    float den = 0.f;
    float2 acc = make_float2(0.f, 0.f);
    const int choff = h * 64 + lane * 2;

    int s_nxt = (n > 0) ? g_srcl[beg] : 0;
    for (int i = 0; i < n; i++) {
        int s = s_nxt;
        if (i + 1 < n) s_nxt = g_srcl[beg + i + 1];
        float as  = g_as0[s * H0 + h];
        float wgt = __expf(leaky02(as + ad));
        float2 v  = *(const float2*)(g_lin0 + (size_t)s * HC0 + choff);
        den   += wgt;
        acc.x  = fmaf(wgt, v.x, acc.x);
        acc.y  = fmaf(wgt, v.y, acc.y);
    }
    float inv = 1.f / (den + 1e-16f);
    float2 bb = *(const float2*)(b0 + choff);
    float2 o;
    o.x = fmaxf(acc.x * inv + bb.x, 0.f);
    o.y = fmaxf(acc.y * inv + bb.y, 0.f);
    *(float2*)(g_feat + (size_t)d * HC0 + choff) = o;
}

// ---------------- CSR aggregation, layer 1: one warp per dst ----------------
__global__ void __launch_bounds__(256)
k_agg1(const float* __restrict__ b1, float* __restrict__ out)
{
    int d    = (blockIdx.x * blockDim.x + threadIdx.x) >> 5;
    int lane = threadIdx.x & 31;
    if (d >= NN) return;

    const int beg = g_row[d];
    const int n   = g_row[d + 1] - beg;
    const float ad = g_ad1[d];

    float den = 0.f;
    float2 acc = make_float2(0.f, 0.f);
    const int choff = lane * 2;

    int s_nxt = (n > 0) ? g_srcl[beg] : 0;
    for (int i = 0; i < n; i++) {
        int s = s_nxt;
        if (i + 1 < n) s_nxt = g_srcl[beg + i + 1];
        float as  = g_as1[s];
        float wgt = __expf(leaky02(as + ad));
        float2 v  = *(const float2*)(g_lin1 + (size_t)s * HC1 + choff);
        den   += wgt;
        acc.x  = fmaf(wgt, v.x, acc.x);
        acc.y  = fmaf(wgt, v.y, acc.y);
    }
    float inv = 1.f / (den + 1e-16f);
    float2 bb = *(const float2*)(b1 + choff);
    float2 o;
    o.x = acc.x * inv + bb.x;
    o.y = acc.y * inv + bb.y;
    *(float2*)(out + (size_t)d * HC1 + choff) = o;
}

// ---------------- launch ----------------
extern "C" void kernel_launch(void* const* d_in, const int* in_sizes, int n_in,
                              void* d_out, int out_size)
{
    const float* x      = (const float*)d_in[0];
    const int*   ei     = (const int*)  d_in[1];
    const float* W0     = (const float*)d_in[2];
    const float* att_s0 = (const float*)d_in[3];
    const float* att_d0 = (const float*)d_in[4];
    const float* b0     = (const float*)d_in[5];
    const float* W1     = (const float*)d_in[6];
    const float* att_s1 = (const float*)d_in[7];
    const float* att_d1 = (const float*)d_in[8];
    const float* b1     = (const float*)d_in[9];

    const int E    = in_sizes[1] / 2;
    const int Etot = E + NN;

    float *p_lin0, *p_feat, *p_lin1, *p_as0, *p_ad0, *p_as1, *p_ad1;
    cudaGetSymbolAddress((void**)&p_lin0, g_lin0);
    cudaGetSymbolAddress((void**)&p_feat, g_feat);
    cudaGetSymbolAddress((void**)&p_lin1, g_lin1);
    cudaGetSymbolAddress((void**)&p_as0,  g_as0);
    cudaGetSymbolAddress((void**)&p_ad0,  g_ad0);
    cudaGetSymbolAddress((void**)&p_as1,  g_as1);
    cudaGetSymbolAddress((void**)&p_ad1,  g_ad1);

    const int TB = 256;

    // ---- CSR build (shared by both layers) ----
    k_zero_deg<<<(NN + TB - 1) / TB, TB>>>();
    k_hist<<<(Etot + TB - 1) / TB, TB>>>(ei, E, Etot);
    k_scan<<<1, 1024>>>();
    k_scatter<<<(Etot + TB - 1) / TB, TB>>>(ei, E, Etot);

    // ---- layer 0 ----
    {
        dim3 grid((NN + 127) / 128, HC0 / 64);
        gemm_nt<128, 64, 32, 8, 8><<<grid, 128>>>(x, W0, p_lin0, NN, HC0, F0);
    }
    k_coef<<<(NN * H0 * 32 + TB - 1) / TB, TB>>>(p_lin0, att_s0, att_d0, p_as0, p_ad0, H0);
    k_agg0<<<(NN * H0 * 32 + TB - 1) / TB, TB>>>(b0);

    // ---- layer 1 ----
    {
        dim3 grid((NN + 127) / 128, HC1 / 64);
        gemm_nt<128, 64, 32, 8, 8><<<grid, 128>>>(p_feat, W1, p_lin1, NN, HC1, HC0);
    }
    k_coef<<<(NN * 32 + TB - 1) / TB, TB>>>(p_lin1, att_s1, att_d1, p_as1, p_ad1, 1);
    k_agg1<<<(NN * 32 + TB - 1) / TB, TB>>>(b1, (float*)d_out);
}

// round 3
// speedup vs baseline: 1.6841x; 1.0798x over previous
#include <cuda_runtime.h>
#include <cstdint>
#include <math.h>

// ---------------- problem constants ----------------
#define NN    50000
#define F0    128
#define H0    4
#define HC0   256
#define HC1   64
#define EMAX  900000

// ---------------- scratch ----------------
__device__ float g_lin0[(size_t)NN * HC0];
__device__ float g_feat[(size_t)NN * HC0];
__device__ float g_lin1[(size_t)NN * HC1];
__device__ float g_as0 [NN * H0];
__device__ float g_ad0 [NN * H0];
__device__ float g_as1 [NN];
__device__ float g_ad1 [NN];
__device__ int   g_deg [NN];
__device__ int   g_row [NN + 1];
__device__ int   g_cur [NN];
__device__ int   g_srcl[EMAX];
__device__ int   g_dstl[EMAX];
__device__ float g_ew0 [(size_t)EMAX * 4];
__device__ float g_ew1 [EMAX];

__device__ __forceinline__ float leaky02(float v) { return v > 0.0f ? v : 0.2f * v; }

__device__ __forceinline__ void edge_sd(const int* __restrict__ ei, int e, int E, int& s, int& d) {
    if (e < E) { s = ei[e]; d = ei[E + e]; } else { s = e - E; d = e - E; }
}

// ---------------- CSR build ----------------
__global__ void k_zero_deg() {
    int i = blockIdx.x * blockDim.x + threadIdx.x;
    if (i < NN) g_deg[i] = 0;
}
__global__ void k_hist(const int* __restrict__ ei, int E, int Etot) {
    int e = blockIdx.x * blockDim.x + threadIdx.x;
    if (e >= Etot) return;
    int s, d; edge_sd(ei, e, E, s, d);
    atomicAdd(&g_deg[d], 1);
}
__global__ void k_scan() {
    __shared__ int ssum[1024];
    const int t  = threadIdx.x;
    const int CH = (NN + 1023) / 1024;
    int beg = t * CH;
    int end = min(beg + CH, NN);
    int s = 0;
    for (int j = beg; j < end; j++) s += g_deg[j];
    ssum[t] = s;
    __syncthreads();
    for (int o = 1; o < 1024; o <<= 1) {
        int v = (t >= o) ? ssum[t - o] : 0;
        __syncthreads();
        ssum[t] += v;
        __syncthreads();
    }
    int run = (t == 0) ? 0 : ssum[t - 1];
    for (int j = beg; j < end; j++) {
        int dv = g_deg[j];
        g_row[j] = run;
        g_cur[j] = run;
        run += dv;
    }
    if (t == 1023) g_row[NN] = run;
}
__global__ void k_scatter(const int* __restrict__ ei, int E, int Etot) {
    int e = blockIdx.x * blockDim.x + threadIdx.x;
    if (e >= Etot) return;
    int s, d; edge_sd(ei, e, E, s, d);
    int pos = atomicAdd(&g_cur[d], 1);
    g_srcl[pos] = s;
    g_dstl[pos] = d;
}

// ---------------- GEMM with fused attention-coefficient epilogue ----------------
// C[M,Nc] = A[M,K] * B[Nc,K]^T ; BN == 64 == one head; epilogue computes
// as_out[row*Hh + head] = <C_row(head cols), att_s>, same for att_d.
template<int BM, int BN, int BK, int TM, int TN>
__global__ void __launch_bounds__((BM/TM)*(BN/TN))
gemm_nt(const float* __restrict__ A, const float* __restrict__ B,
        float* __restrict__ C, int M, int Nc, int K,
        const float* __restrict__ att_s, const float* __restrict__ att_d,
        float* __restrict__ as_out, float* __restrict__ ad_out)
{
    constexpr int THREADS = (BM/TM)*(BN/TN);
    constexpr int BMP = BM + 4;
    constexpr int BNP = BN + 4;
    __shared__ __align__(16) float As[BK][BMP];
    __shared__ __align__(16) float Bs[BK][BNP];

    const int tid = threadIdx.x;
    const int tx  = tid % (BN/TN);
    const int ty  = tid / (BN/TN);
    const int rowBase = blockIdx.x * BM;
    const int colBase = blockIdx.y * BN;

    float acc[TM][TN];
#pragma unroll
    for (int i = 0; i < TM; i++)
#pragma unroll
        for (int j = 0; j < TN; j++) acc[i][j] = 0.f;

    for (int k0 = 0; k0 < K; k0 += BK) {
        constexpr int AF4 = BM * BK / 4;
#pragma unroll
        for (int i = 0; i < AF4 / THREADS; i++) {
            int f  = tid + i * THREADS;
            int r  = f / (BK/4);
            int c4 = f % (BK/4);
            float4 v = make_float4(0.f, 0.f, 0.f, 0.f);
            int gr = rowBase + r;
            if (gr < M) v = *(const float4*)(A + (size_t)gr * K + k0 + c4 * 4);
            As[c4*4+0][r] = v.x; As[c4*4+1][r] = v.y;
            As[c4*4+2][r] = v.z; As[c4*4+3][r] = v.w;
        }
        constexpr int BF4 = BN * BK / 4;
#pragma unroll
        for (int i = 0; i < BF4 / THREADS; i++) {
            int f  = tid + i * THREADS;
            int r  = f / (BK/4);
            int c4 = f % (BK/4);
            float4 v = *(const float4*)(B + (size_t)(colBase + r) * K + k0 + c4 * 4);
            Bs[c4*4+0][r] = v.x; Bs[c4*4+1][r] = v.y;
            Bs[c4*4+2][r] = v.z; Bs[c4*4+3][r] = v.w;
        }
        __syncthreads();

#pragma unroll
        for (int k = 0; k < BK; k++) {
            float a[TM], b[TN];
            const float4* ap = (const float4*)&As[k][ty * TM];
            ((float4*)a)[0] = ap[0]; ((float4*)a)[1] = ap[1];
            const float4* bp = (const float4*)&Bs[k][tx * TN];
            ((float4*)b)[0] = bp[0]; ((float4*)b)[1] = bp[1];
#pragma unroll
            for (int i = 0; i < TM; i++)
#pragma unroll
                for (int j = 0; j < TN; j++)
                    acc[i][j] = fmaf(a[i], b[j], acc[i][j]);
        }
        __syncthreads();
    }

    // ---- store C ----
#pragma unroll
    for (int i = 0; i < TM; i++) {
        int gr = rowBase + ty * TM + i;
        if (gr < M) {
            float* cp = C + (size_t)gr * Nc + colBase + tx * TN;
#pragma unroll
            for (int j = 0; j < TN; j += 4)
                *(float4*)(cp + j) = make_float4(acc[i][j], acc[i][j+1], acc[i][j+2], acc[i][j+3]);
        }
    }

    // ---- fused attention coefficients ----
    {
        const int Hh   = Nc >> 6;          // number of heads
        const int head = colBase >> 6;
        float asv[TN], adv[TN];
#pragma unroll
        for (int j = 0; j < TN; j++) {
            asv[j] = att_s[colBase + tx * TN + j];
            adv[j] = att_d[colBase + tx * TN + j];
        }
#pragma unroll
        for (int i = 0; i < TM; i++) {
            float ps = 0.f, pd = 0.f;
#pragma unroll
            for (int j = 0; j < TN; j++) {
                ps = fmaf(acc[i][j], asv[j], ps);
                pd = fmaf(acc[i][j], adv[j], pd);
            }
            // reduce across the 8 tx lanes (low 3 bits of lane id)
#pragma unroll
            for (int o = 1; o < (BN/TN); o <<= 1) {
                ps += __shfl_xor_sync(0xffffffffu, ps, o);
                pd += __shfl_xor_sync(0xffffffffu, pd, o);
            }
            int gr = rowBase + ty * TM + i;
            if (tx == 0 && gr < M) {
                as_out[gr * Hh + head] = ps;
                ad_out[gr * Hh + head] = pd;
            }
        }
    }
}

// ---------------- per-edge softmax weights ----------------
__global__ void k_ew0(int Etot) {
    int e = blockIdx.x * blockDim.x + threadIdx.x;
    if (e >= Etot) return;
    int s = g_srcl[e];
    int d = g_dstl[e];
    float4 a = *(const float4*)(g_as0 + s * 4);
    float4 b = *(const float4*)(g_ad0 + d * 4);
    float4 w;
    w.x = __expf(leaky02(a.x + b.x));
    w.y = __expf(leaky02(a.y + b.y));
    w.z = __expf(leaky02(a.z + b.z));
    w.w = __expf(leaky02(a.w + b.w));
    *(float4*)(g_ew0 + (size_t)e * 4) = w;
}
__global__ void k_ew1(int Etot) {
    int e = blockIdx.x * blockDim.x + threadIdx.x;
    if (e >= Etot) return;
    g_ew1[e] = __expf(leaky02(g_as1[g_srcl[e]] + g_ad1[g_dstl[e]]));
}

// ---------------- aggregation layer 0: block(128) per dst, all 4 heads ----------------
#define AGG_CH 128
__global__ void __launch_bounds__(128)
k_agg0(const float* __restrict__ b0)
{
    const int d   = blockIdx.x;
    const int tid = threadIdx.x;
    const int h   = tid >> 5;           // head of this thread's channels

    __shared__ int   s_sm [AGG_CH];
    __shared__ float ew_sm[AGG_CH * 4];

    const int beg = g_row[d];
    const int n   = g_row[d + 1] - beg;

    float2 acc = make_float2(0.f, 0.f);
    float  den = 0.f;
    const int choff = tid * 2;

    for (int c0 = 0; c0 < n; c0 += AGG_CH) {
        const int cn = min(AGG_CH, n - c0);
        __syncthreads();
        for (int i = tid; i < cn; i += 128) {
            s_sm[i] = g_srcl[beg + c0 + i];
            *(float4*)(ew_sm + i * 4) = *(const float4*)(g_ew0 + (size_t)(beg + c0 + i) * 4);
        }
        __syncthreads();

        const int P = 4;
        float2 v[P];
#pragma unroll
        for (int j = 0; j < P; j++)
            if (j < cn) v[j] = *(const float2*)(g_lin0 + (size_t)s_sm[j] * HC0 + choff);

        for (int i = 0; i < cn; i++) {
            float  w  = ew_sm[i * 4 + h];
            float2 vv = v[i & (P - 1)];
            int nx = i + P;
            if (nx < cn)
                v[i & (P - 1)] = *(const float2*)(g_lin0 + (size_t)s_sm[nx] * HC0 + choff);
            den  += w;
            acc.x = fmaf(w, vv.x, acc.x);
            acc.y = fmaf(w, vv.y, acc.y);
        }
    }

    float inv = 1.f / (den + 1e-16f);
    float2 bb = *(const float2*)(b0 + choff);
    float2 o;
    o.x = fmaxf(acc.x * inv + bb.x, 0.f);
    o.y = fmaxf(acc.y * inv + bb.y, 0.f);
    *(float2*)(g_feat + (size_t)d * HC0 + choff) = o;
}

// ---------------- aggregation layer 1: warp per dst ----------------
__global__ void __launch_bounds__(256)
k_agg1(const float* __restrict__ b1, float* __restrict__ out)
{
    const int d    = (blockIdx.x * blockDim.x + threadIdx.x) >> 5;
    const int lane = threadIdx.x & 31;
    if (d >= NN) return;

    const int beg = g_row[d];
    const int n   = g_row[d + 1] - beg;

    float2 acc = make_float2(0.f, 0.f);
    float  den = 0.f;
    const int choff = lane * 2;

    for (int base = 0; base < n; base += 32) {
        const int m = min(32, n - base);
        int   s32 = 0;
        float w32 = 0.f;
        if (lane < m) {
            s32 = g_srcl[beg + base + lane];
            w32 = g_ew1 [beg + base + lane];
        }
        const int P = 4;
        float2 v[P];
#pragma unroll
        for (int j = 0; j < P; j++)
            if (j < m) {
                int s = __shfl_sync(0xffffffffu, s32, j);
                v[j] = *(const float2*)(g_lin1 + (size_t)s * HC1 + choff);
            }
        for (int i = 0; i < m; i++) {
            float  w  = __shfl_sync(0xffffffffu, w32, i);
            float2 vv = v[i & (P - 1)];
            int nx = i + P;
            if (nx < m) {
                int s = __shfl_sync(0xffffffffu, s32, nx);
                v[i & (P - 1)] = *(const float2*)(g_lin1 + (size_t)s * HC1 + choff);
            }
            den  += w;
            acc.x = fmaf(w, vv.x, acc.x);
            acc.y = fmaf(w, vv.y, acc.y);
        }
    }

    float inv = 1.f / (den + 1e-16f);
    float2 bb = *(const float2*)(b1 + choff);
    float2 o;
    o.x = acc.x * inv + bb.x;
    o.y = acc.y * inv + bb.y;
    *(float2*)(out + (size_t)d * HC1 + choff) = o;
}

// ---------------- launch ----------------
extern "C" void kernel_launch(void* const* d_in, const int* in_sizes, int n_in,
                              void* d_out, int out_size)
{
    const float* x      = (const float*)d_in[0];
    const int*   ei     = (const int*)  d_in[1];
    const float* W0     = (const float*)d_in[2];
    const float* att_s0 = (const float*)d_in[3];
    const float* att_d0 = (const float*)d_in[4];
    const float* b0     = (const float*)d_in[5];
    const float* W1     = (const float*)d_in[6];
    const float* att_s1 = (const float*)d_in[7];
    const float* att_d1 = (const float*)d_in[8];
    const float* b1     = (const float*)d_in[9];

    const int E    = in_sizes[1] / 2;
    const int Etot = E + NN;

    float *p_lin0, *p_feat, *p_lin1, *p_as0, *p_ad0, *p_as1, *p_ad1;
    cudaGetSymbolAddress((void**)&p_lin0, g_lin0);
    cudaGetSymbolAddress((void**)&p_feat, g_feat);
    cudaGetSymbolAddress((void**)&p_lin1, g_lin1);
    cudaGetSymbolAddress((void**)&p_as0,  g_as0);
    cudaGetSymbolAddress((void**)&p_ad0,  g_ad0);
    cudaGetSymbolAddress((void**)&p_as1,  g_as1);
    cudaGetSymbolAddress((void**)&p_ad1,  g_ad1);

    const int TB = 256;

    // ---- CSR build (shared by both layers) ----
    k_zero_deg<<<(NN + TB - 1) / TB, TB>>>();
    k_hist<<<(Etot + TB - 1) / TB, TB>>>(ei, E, Etot);
    k_scan<<<1, 1024>>>();
    k_scatter<<<(Etot + TB - 1) / TB, TB>>>(ei, E, Etot);

    // ---- layer 0 ----
    {
        dim3 grid((NN + 127) / 128, HC0 / 64);
        gemm_nt<128, 64, 32, 8, 8><<<grid, 128>>>(x, W0, p_lin0, NN, HC0, F0,
                                                  att_s0, att_d0, p_as0, p_ad0);
    }
    k_ew0<<<(Etot + TB - 1) / TB, TB>>>(Etot);
    k_agg0<<<NN, 128>>>(b0);

    // ---- layer 1 ----
    {
        dim3 grid((NN + 127) / 128, HC1 / 64);
        gemm_nt<128, 64, 32, 8, 8><<<grid, 128>>>(p_feat, W1, p_lin1, NN, HC1, HC0,
                                                  att_s1, att_d1, p_as1, p_ad1);
    }
    k_ew1<<<(Etot + TB - 1) / TB, TB>>>(Etot);
    k_agg1<<<(NN * 32 + TB - 1) / TB, TB>>>(b1, (float*)d_out);
}

// round 4
// speedup vs baseline: 1.7603x; 1.0452x over previous
#include <cuda_runtime.h>
#include <cstdint>
#include <math.h>

// ---------------- problem constants ----------------
#define NN    50000
#define F0    128
#define H0    4
#define HC0   256
#define HC1   64
#define EMAX  900000

// ---------------- scratch ----------------
__device__ float g_lin0[(size_t)NN * HC0];
__device__ float g_feat[(size_t)NN * HC0];
__device__ float g_lin1[(size_t)NN * HC1];
__device__ float g_as0 [NN * H0];
__device__ float g_ad0 [NN * H0];
__device__ float g_as1 [NN];
__device__ float g_ad1 [NN];
__device__ int   g_deg [NN];
__device__ int   g_row [NN + 1];
__device__ int   g_cur [NN];
__device__ int   g_srcl[EMAX];
__device__ int   g_dstl[EMAX];
__device__ float g_ew0 [(size_t)EMAX * 4];
__device__ float g_ew1 [EMAX];

__device__ __forceinline__ float leaky02(float v) { return v > 0.0f ? v : 0.2f * v; }

__device__ __forceinline__ void edge_sd(const int* __restrict__ ei, int e, int E, int& s, int& d) {
    if (e < E) { s = ei[e]; d = ei[E + e]; } else { s = e - E; d = e - E; }
}

// ---------------- CSR build ----------------
__global__ void k_zero_deg() {
    int i = blockIdx.x * blockDim.x + threadIdx.x;
    if (i < NN) g_deg[i] = 0;
}
__global__ void k_hist(const int* __restrict__ ei, int E, int Etot) {
    int e = blockIdx.x * blockDim.x + threadIdx.x;
    if (e >= Etot) return;
    int s, d; edge_sd(ei, e, E, s, d);
    atomicAdd(&g_deg[d], 1);
}
__global__ void k_scan() {
    __shared__ int ssum[1024];
    const int t  = threadIdx.x;
    const int CH = (NN + 1023) / 1024;
    int beg = t * CH;
    int end = min(beg + CH, NN);
    int s = 0;
    for (int j = beg; j < end; j++) s += g_deg[j];
    ssum[t] = s;
    __syncthreads();
    for (int o = 1; o < 1024; o <<= 1) {
        int v = (t >= o) ? ssum[t - o] : 0;
        __syncthreads();
        ssum[t] += v;
        __syncthreads();
    }
    int run = (t == 0) ? 0 : ssum[t - 1];
    for (int j = beg; j < end; j++) {
        int dv = g_deg[j];
        g_row[j] = run;
        g_cur[j] = run;
        run += dv;
    }
    if (t == 1023) g_row[NN] = run;
}
__global__ void k_scatter(const int* __restrict__ ei, int E, int Etot) {
    int e = blockIdx.x * blockDim.x + threadIdx.x;
    if (e >= Etot) return;
    int s, d; edge_sd(ei, e, E, s, d);
    int pos = atomicAdd(&g_cur[d], 1);
    g_srcl[pos] = s;
    g_dstl[pos] = d;
}

// ---------------- GEMM (fp32x2 packed FMA) with fused attention-coef epilogue ----------------
template<int BM, int BN, int BK, int TM, int TN>
__global__ void __launch_bounds__((BM/TM)*(BN/TN))
gemm_nt(const float* __restrict__ A, const float* __restrict__ B,
        float* __restrict__ C, int M, int Nc, int K,
        const float* __restrict__ att_s, const float* __restrict__ att_d,
        float* __restrict__ as_out, float* __restrict__ ad_out)
{
    constexpr int THREADS = (BM/TM)*(BN/TN);
    constexpr int BMP = BM + 4;
    constexpr int BNP = BN + 4;
    __shared__ __align__(16) float As[BK][BMP];
    __shared__ __align__(16) float Bs[BK][BNP];

    const int tid = threadIdx.x;
    const int tx  = tid % (BN/TN);
    const int ty  = tid / (BN/TN);
    const int rowBase = blockIdx.x * BM;
    const int colBase = blockIdx.y * BN;

    // packed accumulators: acc2[i][j2] = {acc[i][2*j2], acc[i][2*j2+1]}
    unsigned long long acc2[TM][TN/2];
#pragma unroll
    for (int i = 0; i < TM; i++)
#pragma unroll
        for (int j = 0; j < TN/2; j++) acc2[i][j] = 0ull;

    for (int k0 = 0; k0 < K; k0 += BK) {
        constexpr int AF4 = BM * BK / 4;
#pragma unroll
        for (int i = 0; i < AF4 / THREADS; i++) {
            int f  = tid + i * THREADS;
            int r  = f / (BK/4);
            int c4 = f % (BK/4);
            float4 v = make_float4(0.f, 0.f, 0.f, 0.f);
            int gr = rowBase + r;
            if (gr < M) v = *(const float4*)(A + (size_t)gr * K + k0 + c4 * 4);
            As[c4*4+0][r] = v.x; As[c4*4+1][r] = v.y;
            As[c4*4+2][r] = v.z; As[c4*4+3][r] = v.w;
        }
        constexpr int BF4 = BN * BK / 4;
#pragma unroll
        for (int i = 0; i < BF4 / THREADS; i++) {
            int f  = tid + i * THREADS;
            int r  = f / (BK/4);
            int c4 = f % (BK/4);
            float4 v = *(const float4*)(B + (size_t)(colBase + r) * K + k0 + c4 * 4);
            Bs[c4*4+0][r] = v.x; Bs[c4*4+1][r] = v.y;
            Bs[c4*4+2][r] = v.z; Bs[c4*4+3][r] = v.w;
        }
        __syncthreads();

#pragma unroll
        for (int k = 0; k < BK; k++) {
            float a[TM];
            const float4* ap = (const float4*)&As[k][ty * TM];
            ((float4*)a)[0] = ap[0]; ((float4*)a)[1] = ap[1];
            unsigned long long b2[TN/2];
            const unsigned long long* bp = (const unsigned long long*)&Bs[k][tx * TN];
#pragma unroll
            for (int j = 0; j < TN/2; j++) b2[j] = bp[j];
#pragma unroll
            for (int i = 0; i < TM; i++) {
                unsigned long long a2;
                asm("mov.b64 %0, {%1, %1};" : "=l"(a2) : "f"(a[i]));
#pragma unroll
                for (int j = 0; j < TN/2; j++)
                    asm("fma.rn.f32x2 %0, %1, %2, %0;"
                        : "+l"(acc2[i][j]) : "l"(a2), "l"(b2[j]));
            }
        }
        __syncthreads();
    }

    // ---- store C (acc2 rows are exactly 8 contiguous floats) ----
#pragma unroll
    for (int i = 0; i < TM; i++) {
        int gr = rowBase + ty * TM + i;
        if (gr < M) {
            const float* af = (const float*)acc2[i];
            float* cp = C + (size_t)gr * Nc + colBase + tx * TN;
            *(float4*)(cp)     = make_float4(af[0], af[1], af[2], af[3]);
            *(float4*)(cp + 4) = make_float4(af[4], af[5], af[6], af[7]);
        }
    }

    // ---- fused attention coefficients (BN==64 == one head) ----
    {
        const int Hh   = Nc >> 6;
        const int head = colBase >> 6;
        float asv[TN], adv[TN];
#pragma unroll
        for (int j = 0; j < TN; j++) {
            asv[j] = att_s[colBase + tx * TN + j];
            adv[j] = att_d[colBase + tx * TN + j];
        }
#pragma unroll
        for (int i = 0; i < TM; i++) {
            const float* af = (const float*)acc2[i];
            float ps = 0.f, pd = 0.f;
#pragma unroll
            for (int j = 0; j < TN; j++) {
                ps = fmaf(af[j], asv[j], ps);
                pd = fmaf(af[j], adv[j], pd);
            }
#pragma unroll
            for (int o = 1; o < (BN/TN); o <<= 1) {
                ps += __shfl_xor_sync(0xffffffffu, ps, o);
                pd += __shfl_xor_sync(0xffffffffu, pd, o);
            }
            int gr = rowBase + ty * TM + i;
            if (tx == 0 && gr < M) {
                as_out[gr * Hh + head] = ps;
                ad_out[gr * Hh + head] = pd;
            }
        }
    }
}

// ---------------- per-edge softmax weights ----------------
__global__ void k_ew0(int Etot) {
    int e = blockIdx.x * blockDim.x + threadIdx.x;
    if (e >= Etot) return;
    int s = g_srcl[e];
    int d = g_dstl[e];
    float4 a = *(const float4*)(g_as0 + s * 4);
    float4 b = *(const float4*)(g_ad0 + d * 4);
    float4 w;
    w.x = __expf(leaky02(a.x + b.x));
    w.y = __expf(leaky02(a.y + b.y));
    w.z = __expf(leaky02(a.z + b.z));
    w.w = __expf(leaky02(a.w + b.w));
    *(float4*)(g_ew0 + (size_t)e * 4) = w;
}
__global__ void k_ew1(int Etot) {
    int e = blockIdx.x * blockDim.x + threadIdx.x;
    if (e >= Etot) return;
    g_ew1[e] = __expf(leaky02(g_as1[g_srcl[e]] + g_ad1[g_dstl[e]]));
}

// ---------------- aggregation layer 0: block(128) per dst ----------------
#define AGG_CH 128
__global__ void __launch_bounds__(128)
k_agg0(const float* __restrict__ b0)
{
    const int d   = blockIdx.x;
    const int tid = threadIdx.x;
    const int h   = tid >> 5;

    __shared__ int   s_sm [AGG_CH];
    __shared__ float ew_sm[AGG_CH * 4];

    const int beg = g_row[d];
    const int n   = g_row[d + 1] - beg;

    float2 acc = make_float2(0.f, 0.f);
    float  den = 0.f;
    const int choff = tid * 2;

    for (int c0 = 0; c0 < n; c0 += AGG_CH) {
        const int cn = min(AGG_CH, n - c0);
        __syncthreads();
        for (int i = tid; i < cn; i += 128) {
            s_sm[i] = g_srcl[beg + c0 + i];
            *(float4*)(ew_sm + i * 4) = *(const float4*)(g_ew0 + (size_t)(beg + c0 + i) * 4);
        }
        __syncthreads();

        const int P = 4;
        float2 v[P];
#pragma unroll
        for (int j = 0; j < P; j++)
            if (j < cn) v[j] = *(const float2*)(g_lin0 + (size_t)s_sm[j] * HC0 + choff);

        for (int i = 0; i < cn; i++) {
            float  w  = ew_sm[i * 4 + h];
            float2 vv = v[i & (P - 1)];
            int nx = i + P;
            if (nx < cn)
                v[i & (P - 1)] = *(const float2*)(g_lin0 + (size_t)s_sm[nx] * HC0 + choff);
            den  += w;
            acc.x = fmaf(w, vv.x, acc.x);
            acc.y = fmaf(w, vv.y, acc.y);
        }
    }

    float inv = 1.f / (den + 1e-16f);
    float2 bb = *(const float2*)(b0 + choff);
    float2 o;
    o.x = fmaxf(acc.x * inv + bb.x, 0.f);
    o.y = fmaxf(acc.y * inv + bb.y, 0.f);
    *(float2*)(g_feat + (size_t)d * HC0 + choff) = o;
}

// ---------------- aggregation layer 1: warp per dst ----------------
__global__ void __launch_bounds__(256)
k_agg1(const float* __restrict__ b1, float* __restrict__ out)
{
    const int d    = (blockIdx.x * blockDim.x + threadIdx.x) >> 5;
    const int lane = threadIdx.x & 31;
    if (d >= NN) return;

    const int beg = g_row[d];
    const int n   = g_row[d + 1] - beg;

    float2 acc = make_float2(0.f, 0.f);
    float  den = 0.f;
    const int choff = lane * 2;

    for (int base = 0; base < n; base += 32) {
        const int m = min(32, n - base);
        int   s32 = 0;
        float w32 = 0.f;
        if (lane < m) {
            s32 = g_srcl[beg + base + lane];
            w32 = g_ew1 [beg + base + lane];
        }
        const int P = 4;
        float2 v[P];
#pragma unroll
        for (int j = 0; j < P; j++)
            if (j < m) {
                int s = __shfl_sync(0xffffffffu, s32, j);
                v[j] = *(const float2*)(g_lin1 + (size_t)s * HC1 + choff);
            }
        for (int i = 0; i < m; i++) {
            float  w  = __shfl_sync(0xffffffffu, w32, i);
            float2 vv = v[i & (P - 1)];
            int nx = i + P;
            if (nx < m) {
                int s = __shfl_sync(0xffffffffu, s32, nx);
                v[i & (P - 1)] = *(const float2*)(g_lin1 + (size_t)s * HC1 + choff);
            }
            den  += w;
            acc.x = fmaf(w, vv.x, acc.x);
            acc.y = fmaf(w, vv.y, acc.y);
        }
    }

    float inv = 1.f / (den + 1e-16f);
    float2 bb = *(const float2*)(b1 + choff);
    float2 o;
    o.x = acc.x * inv + bb.x;
    o.y = acc.y * inv + bb.y;
    *(float2*)(out + (size_t)d * HC1 + choff) = o;
}

// ---------------- launch ----------------
extern "C" void kernel_launch(void* const* d_in, const int* in_sizes, int n_in,
                              void* d_out, int out_size)
{
    const float* x      = (const float*)d_in[0];
    const int*   ei     = (const int*)  d_in[1];
    const float* W0     = (const float*)d_in[2];
    const float* att_s0 = (const float*)d_in[3];
    const float* att_d0 = (const float*)d_in[4];
    const float* b0     = (const float*)d_in[5];
    const float* W1     = (const float*)d_in[6];
    const float* att_s1 = (const float*)d_in[7];
    const float* att_d1 = (const float*)d_in[8];
    const float* b1     = (const float*)d_in[9];

    const int E    = in_sizes[1] / 2;
    const int Etot = E + NN;

    float *p_lin0, *p_feat, *p_lin1, *p_as0, *p_ad0, *p_as1, *p_ad1;
    cudaGetSymbolAddress((void**)&p_lin0, g_lin0);
    cudaGetSymbolAddress((void**)&p_feat, g_feat);
    cudaGetSymbolAddress((void**)&p_lin1, g_lin1);
    cudaGetSymbolAddress((void**)&p_as0,  g_as0);
    cudaGetSymbolAddress((void**)&p_ad0,  g_ad0);
    cudaGetSymbolAddress((void**)&p_as1,  g_as1);
    cudaGetSymbolAddress((void**)&p_ad1,  g_ad1);

    // one-time side-stream + events (created on the uncaptured correctness call,
    // reused identically in every captured/replayed launch)
    static cudaStream_t sB = nullptr;
    static cudaEvent_t  evFork = nullptr, evJoin = nullptr;
    if (sB == nullptr) {
        cudaStreamCreateWithFlags(&sB, cudaStreamNonBlocking);
        cudaEventCreateWithFlags(&evFork, cudaEventDisableTiming);
        cudaEventCreateWithFlags(&evJoin, cudaEventDisableTiming);
    }

    const int TB = 256;

    // ---- fork: CSR build on side stream, concurrent with GEMM0 ----
    cudaEventRecord(evFork, 0);
    cudaStreamWaitEvent(sB, evFork, 0);
    k_zero_deg<<<(NN + TB - 1) / TB, TB, 0, sB>>>();
    k_hist<<<(Etot + TB - 1) / TB, TB, 0, sB>>>(ei, E, Etot);
    k_scan<<<1, 1024, 0, sB>>>();
    k_scatter<<<(Etot + TB - 1) / TB, TB, 0, sB>>>(ei, E, Etot);
    cudaEventRecord(evJoin, sB);

    // ---- layer 0 GEMM (main stream, overlapped with CSR) ----
    {
        dim3 grid((NN + 127) / 128, HC0 / 64);
        gemm_nt<128, 64, 32, 8, 8><<<grid, 128>>>(x, W0, p_lin0, NN, HC0, F0,
                                                  att_s0, att_d0, p_as0, p_ad0);
    }

    // ---- join: everything after needs the CSR ----
    cudaStreamWaitEvent(0, evJoin, 0);

    k_ew0<<<(Etot + TB - 1) / TB, TB>>>(Etot);
    k_agg0<<<NN, 128>>>(b0);

    // ---- layer 1 ----
    {
        dim3 grid((NN + 127) / 128, HC1 / 64);
        gemm_nt<128, 64, 32, 8, 8><<<grid, 128>>>(p_feat, W1, p_lin1, NN, HC1, HC0,
                                                  att_s1, att_d1, p_as1, p_ad1);
    }
    k_ew1<<<(Etot + TB - 1) / TB, TB>>>(Etot);
    k_agg1<<<(NN * 32 + TB - 1) / TB, TB>>>(b1, (float*)d_out);
}